// round 11
// baseline (speedup 1.0000x reference)
#include <cuda_runtime.h>

#define BB 4
#define TT 512
#define TPQ 1024
#define CC 32
#define KK 128
#define EPSF 2.220446049250313e-16f
#define NB 256          // total blocks (all resident: 2 CTAs/SM * 148 = 296 >= 256)
#define NPREP 16        // prep blocks (4 per batch)
#define QPB 16          // queries per block (NB*QPB = 4096)
#define GUARD (BB * TT) // zero guard row index in g_PS

// Scratch
__device__ float2   g_AD[CC * CC];             // (softplus(alpha), softplus(delta)+eps)
__device__ float    g_spmu[CC];
__device__ float    g_fp[KK];
__device__ float    g_st[BB * TT];             // per-batch times grouped by type
__device__ float    g_PS[(BB * TT + 1) * CC];  // prefix sums + zero guard row
__device__ int      g_off[BB * CC];
__device__ int      g_cnt[BB * CC];
__device__ unsigned g_count = 0;               // barrier arrival counter
__device__ unsigned g_gen   = 0;               // barrier generation

__device__ __forceinline__ float softplus_f(float x) {
    return fmaxf(x, 0.f) + log1pf(__expf(-fabsf(x)));
}

__global__ void __launch_bounds__(256, 2) fused_kernel(
    const int* __restrict__ pe, const float* __restrict__ pt,
    const float* __restrict__ tt,
    const float* __restrict__ mu, const float* __restrict__ alpha,
    const float* __restrict__ delta, const float* __restrict__ cf,
    const int* __restrict__ ftc, float* __restrict__ out)
{
    // prep-phase smem
    __shared__ float s_t[TT];
    __shared__ int   s_ev[TT];
    __shared__ float s_ct[TT];
    __shared__ int   p_cnt[CC], p_off[CC];
    __shared__ float s_e[KK], s_den[CC];
    __shared__ float s_max;
    // query-phase smem
    __shared__ float2 sAD[CC * CC];      // 8KB
    __shared__ float  s_st[TT];          // 2KB
    __shared__ float  sfp[KK], sspmu[CC];
    __shared__ int    sftc[KK];
    __shared__ int    s_off[CC], s_cnt[CC];
    __shared__ int    s_row[8][2][CC];   // per-warp resolved PS rows

    const int tid  = threadIdx.x;
    const int w    = tid >> 5;
    const int lane = tid & 31;
    const int bx   = blockIdx.x;

    if (tid < KK) sftc[tid] = ftc[tid];          // independent of prep

    // ============================ PREP (blocks 0..15) ============================
    if (bx < NPREP) {
        const int b  = bx >> 2;
        const int ty = (bx & 3) * 8 + w;         // this warp's coarse type

        for (int i = tid; i < TT; i += 256) {
            s_t[i]  = pt[b * TT + i];
            s_ev[i] = pe[b * TT + i];
        }
        if (bx == 0 && w == 7) {                 // max(cf)
            float m = fmaxf(fmaxf(cf[lane], cf[lane + 32]),
                            fmaxf(cf[lane + 64], cf[lane + 96]));
            #pragma unroll
            for (int d = 16; d > 0; d >>= 1)
                m = fmaxf(m, __shfl_xor_sync(0xffffffffu, m, d));
            if (lane == 0) s_max = m;
        }
        __syncthreads();

        // counts: warp w counts types w, w+8, w+16, w+24
        #pragma unroll
        for (int r = 0; r < 4; r++) {
            int t = w + 8 * r;
            unsigned cnt = 0;
            #pragma unroll
            for (int it = 0; it < TT / 32; it++)
                cnt += __popc(__ballot_sync(0xffffffffu, s_ev[it * 32 + lane] == t));
            if (lane == 0) p_cnt[t] = (int)cnt;
        }
        if (bx == 0) {                           // param tables
            #pragma unroll
            for (int r = 0; r < 4; r++) {
                int i = tid + 256 * r;
                g_AD[i] = make_float2(softplus_f(alpha[i]), softplus_f(delta[i]) + EPSF);
            }
            if (tid < CC) g_spmu[tid] = softplus_f(mu[tid]);
            if (tid < CC) g_PS[(size_t)GUARD * CC + tid] = 0.f;
            if (tid < KK) s_e[tid] = expf(cf[tid] - s_max);
        }
        __syncthreads();

        if (w == 0) {                            // exclusive scan of counts
            int v = p_cnt[lane];
            int incl = v;
            #pragma unroll
            for (int d = 1; d < 32; d <<= 1) {
                int u = __shfl_up_sync(0xffffffffu, incl, d);
                if (lane >= d) incl += u;
            }
            p_off[lane] = incl - v;
            if ((bx & 3) == 0) {
                g_off[b * CC + lane] = incl - v;
                g_cnt[b * CC + lane] = v;
            }
        }
        if (bx == 0 && tid < CC) {
            float d = 0.f;
            for (int k = 0; k < KK; k++)
                if (sftc[k] == tid) d += s_e[k];
            s_den[tid] = d;
        }
        __syncthreads();

        if (bx == 0 && tid < KK) g_fp[tid] = s_e[tid] / s_den[sftc[tid]];

        // stable compaction for type ty (warp w)
        {
            int pos = p_off[ty];
            #pragma unroll
            for (int it = 0; it < TT / 32; it++) {
                int i = it * 32 + lane;
                bool hit = (s_ev[i] == ty);
                unsigned m = __ballot_sync(0xffffffffu, hit);
                if (hit) {
                    int rank = __popc(m & ((1u << lane) - 1u));
                    float tv = s_t[i];
                    s_ct[pos + rank] = tv;
                    g_st[b * TT + pos + rank] = tv;
                }
                pos += __popc(m);
            }
        }
        __syncwarp();

        // prefix sums: thread (ty, lane=c)
        {
            int off = p_off[ty];
            int n   = p_cnt[ty];
            float D = softplus_f(delta[ty * CC + lane]) + EPSF;
            float s = 0.f;
            for (int j = 0; j < n; j++) {
                s += __expf(D * s_ct[off + j]);
                g_PS[(size_t)(b * TT + off + j) * CC + lane] = s;
            }
        }
        __syncthreads();
    }

    // ===================== GRID BARRIER (all NB blocks resident) =====================
    if (tid == 0) {
        __threadfence();
        unsigned gen = *(volatile unsigned*)&g_gen;
        unsigned t = atomicAdd(&g_count, 1u);
        if (t == NB - 1u) {
            atomicExch(&g_count, 0u);
            __threadfence();
            atomicExch(&g_gen, gen + 1u);
        } else {
            while (*(volatile unsigned*)&g_gen == gen) __nanosleep(100);
        }
        __threadfence();
    }
    __syncthreads();

    // ============================ QUERY PHASE (all blocks) ============================
    const int qbase = bx * QPB;
    const int b     = qbase >> 10;               // TPQ = 1024

    #pragma unroll
    for (int i = tid; i < CC * CC; i += 256) sAD[i] = g_AD[i];
    #pragma unroll
    for (int i = tid; i < TT; i += 256) s_st[i] = g_st[b * TT + i];
    if (tid < KK) sfp[tid] = g_fp[tid];
    if (tid < CC) {
        sspmu[tid] = g_spmu[tid];
        s_off[tid] = g_off[b * CC + tid];
        s_cnt[tid] = g_cnt[b * CC + tid];
    }
    __syncthreads();

    const float tq0 = tt[qbase + 2 * w];
    const float tq1 = tt[qbase + 2 * w + 1];

    // per-lane binary search (lane = type), 2 queries
    {
        const int off = s_off[lane];
        const int cnt = s_cnt[lane];
        int lo0 = 0, hi0 = cnt, lo1 = 0, hi1 = cnt;
        while (lo0 < hi0) {
            int mid = (lo0 + hi0) >> 1;
            if (s_st[off + mid] < tq0) lo0 = mid + 1; else hi0 = mid;
        }
        while (lo1 < hi1) {
            int mid = (lo1 + hi1) >> 1;
            if (s_st[off + mid] < tq1) lo1 = mid + 1; else hi1 = mid;
        }
        s_row[w][0][lane] = (lo0 > 0) ? (b * TT + off + lo0 - 1) : GUARD;
        s_row[w][1][lane] = (lo1 > 0) ? (b * TT + off + lo1 - 1) : GUARD;
    }
    __syncwarp();

    float acc0 = 0.f, acc1 = 0.f;
    #pragma unroll 8
    for (int e = 0; e < CC; e++) {
        float2 ad = sAD[e * CC + lane];
        int r0 = s_row[w][0][e];
        int r1 = s_row[w][1][e];
        float ps0 = g_PS[(size_t)r0 * CC + lane];   // L2-resident, coalesced
        float ps1 = g_PS[(size_t)r1 * CC + lane];
        acc0 = fmaf(ad.x * __expf(-ad.y * tq0), ps0, acc0);
        acc1 = fmaf(ad.x * __expf(-ad.y * tq1), ps1, acc1);
    }
    acc0 += sspmu[lane];
    acc1 += sspmu[lane];

    // shuffle epilogue, coalesced stores
    {
        size_t base0 = (size_t)(qbase + 2 * w) * KK;
        size_t base1 = (size_t)(qbase + 2 * w + 1) * KK;
        #pragma unroll
        for (int s4 = 0; s4 < 4; s4++) {
            int k = s4 * 32 + lane;
            int c = sftc[k];
            float fp = sfp[k];
            out[base0 + k] = __shfl_sync(0xffffffffu, acc0, c) * fp;
            out[base1 + k] = __shfl_sync(0xffffffffu, acc1, c) * fp;
        }
    }
}

extern "C" void kernel_launch(void* const* d_in, const int* in_sizes, int n_in,
                              void* d_out, int out_size) {
    const int*   pe    = (const int*)d_in[0];
    const float* pt    = (const float*)d_in[1];
    const float* tt    = (const float*)d_in[2];
    const float* mu    = (const float*)d_in[3];
    const float* alpha = (const float*)d_in[4];
    const float* delta = (const float*)d_in[5];
    const float* cf    = (const float*)d_in[6];
    const int*   ftc   = (const int*)d_in[7];
    float* out = (float*)d_out;

    fused_kernel<<<NB, 256>>>(pe, pt, tt, mu, alpha, delta, cf, ftc, out);
}